// round 2
// baseline (speedup 1.0000x reference)
#include <cuda_runtime.h>

#define D 128
#define TM 64           // rows per GEMM block
#define GEMM_THREADS 256

static const int MAX_NU = 100000;
static const int MAX_NI = 50000;

// Scratch (static device globals: allocation-free at launch time)
__device__ float g_agg_u[(size_t)MAX_NU * D];
__device__ float g_agg_i[(size_t)MAX_NI * D];
__device__ float g_h1_u[(size_t)MAX_NU * D];
__device__ float g_h1_i[(size_t)MAX_NI * D];
__device__ float g_inv_u[MAX_NU];
__device__ float g_inv_i[MAX_NI];

// ---------------------------------------------------------------------------
// Utility kernels
// ---------------------------------------------------------------------------
__global__ void k_zero(float* __restrict__ p, int n4) {
    int i = blockIdx.x * blockDim.x + threadIdx.x;
    if (i < n4) ((float4*)p)[i] = make_float4(0.f, 0.f, 0.f, 0.f);
}

__global__ void k_count(const int* __restrict__ dst, float* __restrict__ cnt, int E) {
    int e = blockIdx.x * blockDim.x + threadIdx.x;
    if (e < E) atomicAdd(&cnt[dst[e]], 1.0f);
}

__global__ void k_recip(float* __restrict__ c, int n) {
    int i = blockIdx.x * blockDim.x + threadIdx.x;
    if (i < n) c[i] = 1.0f / fmaxf(c[i], 1.0f);
}

// One warp per edge: gather 512B of source features (coalesced), scatter via
// fp32 atomics into the destination row. Dest buffers fit in L2.
__global__ void k_scatter(const float* __restrict__ feat,
                          const int* __restrict__ src,
                          const int* __restrict__ dst,
                          float* __restrict__ agg, int E) {
    long long t = (long long)blockIdx.x * blockDim.x + threadIdx.x;
    int e    = (int)(t >> 5);
    int lane = (int)(t & 31);
    if (e >= E) return;
    int s = src[e];
    int d = dst[e];
    float4 v = ((const float4*)(feat + (long long)s * D))[lane];
    float* b = agg + (long long)d * D + lane * 4;
    atomicAdd(b + 0, v.x);
    atomicAdd(b + 1, v.y);
    atomicAdd(b + 2, v.z);
    atomicAdd(b + 3, v.w);
}

// ---------------------------------------------------------------------------
// Fused SAGE GEMM:
//   out[m,:] = act( (agg[m,:]*inv[m]) @ Wl^T  +  x[m,:] @ (Wr+Lw)^T  + (bl+lb) )
// Two phases over the same accumulators: phase 0 uses (agg*inv, Wl),
// phase 1 uses (x, Wr+Lw). K = N = 128 fixed. Tile: 64 rows/block,
// 256 threads, each thread computes 8 rows x 4 cols.
// Shared: Ws[128][129] (padded, conflict-free col-strided reads) + As[64][128].
// ---------------------------------------------------------------------------
__global__ __launch_bounds__(GEMM_THREADS) void k_gemm(
    const float* __restrict__ agg, const float* __restrict__ inv,
    const float* __restrict__ x,
    const float* __restrict__ Wl, const float* __restrict__ Wr,
    const float* __restrict__ Lw,
    const float* __restrict__ bl, const float* __restrict__ lb,
    float* __restrict__ out, int M, int do_relu) {
    extern __shared__ float sm[];
    float(*Ws)[129] = (float(*)[129])sm;                 // [128][129]
    float(*As)[D]   = (float(*)[D])(sm + 128 * 129);     // [64][128]

    const int tid = threadIdx.x;
    const int tx = tid & 31;        // -> output cols {tx, tx+32, tx+64, tx+96}
    const int ty = tid >> 5;        // -> output rows ty*8 .. ty*8+7
    const int row0 = blockIdx.x * TM;

    float acc[8][4];
#pragma unroll
    for (int i = 0; i < 8; i++)
#pragma unroll
        for (int j = 0; j < 4; j++) acc[i][j] = 0.f;

    for (int p = 0; p < 2; p++) {
        __syncthreads();  // protect shared reuse between phases
        // Load weights: phase 1 fuses Wr + Lw on the fly.
        const float* W = p ? Wr : Wl;
        for (int i = tid; i < 128 * 128; i += GEMM_THREADS) {
            float w = W[i];
            if (p) w += Lw[i];
            Ws[i >> 7][i & 127] = w;
        }
        // Load A tile: phase 0 applies the mean scaling (1/cnt) on the fly.
        const float* A = p ? x : agg;
        for (int i = tid; i < TM * D; i += GEMM_THREADS) {
            int r = i >> 7, k = i & 127;
            int gr = row0 + r;
            float v = 0.f;
            if (gr < M) {
                v = A[(long long)gr * D + k];
                if (!p) v *= inv[gr];
            }
            As[r][k] = v;
        }
        __syncthreads();

#pragma unroll 4
        for (int k = 0; k < D; k++) {
            float a[8], w[4];
#pragma unroll
            for (int i = 0; i < 8; i++) a[i] = As[ty * 8 + i][k];   // broadcast
#pragma unroll
            for (int j = 0; j < 4; j++) w[j] = Ws[tx + 32 * j][k];  // conflict-free
#pragma unroll
            for (int i = 0; i < 8; i++)
#pragma unroll
                for (int j = 0; j < 4; j++)
                    acc[i][j] = fmaf(a[i], w[j], acc[i][j]);
        }
    }

    // Epilogue: fused double-bias + optional ReLU
    float bias[4];
#pragma unroll
    for (int j = 0; j < 4; j++) {
        int c = tx + 32 * j;
        bias[j] = bl[c] + lb[c];
    }
#pragma unroll
    for (int i = 0; i < 8; i++) {
        int gr = row0 + ty * 8 + i;
        if (gr >= M) continue;
#pragma unroll
        for (int j = 0; j < 4; j++) {
            float v = acc[i][j] + bias[j];
            if (do_relu) v = fmaxf(v, 0.f);
            out[(long long)gr * D + tx + 32 * j] = v;
        }
    }
}

// ---------------------------------------------------------------------------
// Launch
// ---------------------------------------------------------------------------
extern "C" void kernel_launch(void* const* d_in, const int* in_sizes, int n_in,
                              void* d_out, int out_size) {
    const float* x_user = (const float*)d_in[0];
    const float* x_item = (const float*)d_in[1];
    const int* ui_src = (const int*)d_in[2];
    const int* ui_dst = (const int*)d_in[3];
    const int* iu_src = (const int*)d_in[4];
    const int* iu_dst = (const int*)d_in[5];
    const float* W1l_ui = (const float*)d_in[6];
    const float* b1_ui  = (const float*)d_in[7];
    const float* W1r_ui = (const float*)d_in[8];
    const float* W1l_iu = (const float*)d_in[9];
    const float* b1_iu  = (const float*)d_in[10];
    const float* W1r_iu = (const float*)d_in[11];
    const float* L1W_u  = (const float*)d_in[12];
    const float* L1b_u  = (const float*)d_in[13];
    const float* L1W_i  = (const float*)d_in[14];
    const float* L1b_i  = (const float*)d_in[15];
    const float* W2l_ui = (const float*)d_in[16];
    const float* b2_ui  = (const float*)d_in[17];
    const float* W2r_ui = (const float*)d_in[18];
    const float* W2l_iu = (const float*)d_in[19];
    const float* b2_iu  = (const float*)d_in[20];
    const float* W2r_iu = (const float*)d_in[21];
    const float* L2W_u  = (const float*)d_in[22];
    const float* L2b_u  = (const float*)d_in[23];
    const float* L2W_i  = (const float*)d_in[24];
    const float* L2b_i  = (const float*)d_in[25];

    const int N_U = in_sizes[0] / D;
    const int N_I = in_sizes[1] / D;
    const int E   = in_sizes[2];

    float *agg_u, *agg_i, *h1_u, *h1_i, *inv_u, *inv_i;
    cudaGetSymbolAddress((void**)&agg_u, g_agg_u);
    cudaGetSymbolAddress((void**)&agg_i, g_agg_i);
    cudaGetSymbolAddress((void**)&h1_u, g_h1_u);
    cudaGetSymbolAddress((void**)&h1_i, g_h1_i);
    cudaGetSymbolAddress((void**)&inv_u, g_inv_u);
    cudaGetSymbolAddress((void**)&inv_i, g_inv_i);

    float* out_u = (float*)d_out;
    float* out_i = out_u + (size_t)N_U * D;

    const int smem_bytes = (128 * 129 + TM * D) * (int)sizeof(float);
    cudaFuncSetAttribute(k_gemm, cudaFuncAttributeMaxDynamicSharedMemorySize,
                         smem_bytes);

    const int ZT = 256;
    auto zb = [](int n4) { return (n4 + 255) / 256; };
    const int eb  = (E + 255) / 256;
    const int sb  = (int)(((long long)E * 32 + 255) / 256);
    const int gbU = (N_U + TM - 1) / TM;
    const int gbI = (N_I + TM - 1) / TM;

    // --- degree counts (shared by both layers) ---
    k_zero<<<zb(N_U / 4), ZT>>>(inv_u, N_U / 4);
    k_zero<<<zb(N_I / 4), ZT>>>(inv_i, N_I / 4);
    k_count<<<eb, 256>>>(iu_dst, inv_u, E);
    k_count<<<eb, 256>>>(ui_dst, inv_i, E);
    k_recip<<<(N_U + 255) / 256, 256>>>(inv_u, N_U);
    k_recip<<<(N_I + 255) / 256, 256>>>(inv_i, N_I);

    // --- layer 1 aggregation ---
    k_zero<<<zb(N_U * D / 4), ZT>>>(agg_u, N_U * D / 4);
    k_zero<<<zb(N_I * D / 4), ZT>>>(agg_i, N_I * D / 4);
    k_scatter<<<sb, 256>>>(x_item, iu_src, iu_dst, agg_u, E);
    k_scatter<<<sb, 256>>>(x_user, ui_src, ui_dst, agg_i, E);

    // --- layer 1 fused GEMMs (relu) ---
    k_gemm<<<gbU, GEMM_THREADS, smem_bytes>>>(agg_u, inv_u, x_user,
                                              W1l_iu, W1r_iu, L1W_u,
                                              b1_iu, L1b_u, h1_u, N_U, 1);
    k_gemm<<<gbI, GEMM_THREADS, smem_bytes>>>(agg_i, inv_i, x_item,
                                              W1l_ui, W1r_ui, L1W_i,
                                              b1_ui, L1b_i, h1_i, N_I, 1);

    // --- layer 2 aggregation ---
    k_zero<<<zb(N_U * D / 4), ZT>>>(agg_u, N_U * D / 4);
    k_zero<<<zb(N_I * D / 4), ZT>>>(agg_i, N_I * D / 4);
    k_scatter<<<sb, 256>>>(h1_i, iu_src, iu_dst, agg_u, E);
    k_scatter<<<sb, 256>>>(h1_u, ui_src, ui_dst, agg_i, E);

    // --- layer 2 fused GEMMs (no relu) ---
    k_gemm<<<gbU, GEMM_THREADS, smem_bytes>>>(agg_u, inv_u, h1_u,
                                              W2l_iu, W2r_iu, L2W_u,
                                              b2_iu, L2b_u, out_u, N_U, 0);
    k_gemm<<<gbI, GEMM_THREADS, smem_bytes>>>(agg_i, inv_i, h1_i,
                                              W2l_ui, W2r_ui, L2W_i,
                                              b2_ui, L2b_i, out_i, N_I, 0);
}

// round 3
// speedup vs baseline: 1.4060x; 1.4060x over previous
#include <cuda_runtime.h>

#define D 128
#define TM 64
#define GEMM_THREADS 256

static const int MAX_NU = 100000;
static const int MAX_NI = 50000;
static const int MAX_E  = 300000;

// Scratch (static device globals: allocation-free at launch time)
__device__ float g_agg_u[(size_t)MAX_NU * D];
__device__ float g_agg_i[(size_t)MAX_NI * D];
__device__ float g_h1_u[(size_t)MAX_NU * D];
__device__ float g_h1_i[(size_t)MAX_NI * D];
__device__ int g_cnt_u[MAX_NU];
__device__ int g_cnt_i[MAX_NI];
__device__ int g_rowptr_u[MAX_NU + 1];
__device__ int g_rowptr_i[MAX_NI + 1];
__device__ int g_cursor_u[MAX_NU];
__device__ int g_cursor_i[MAX_NI];
__device__ int g_eidx_u[MAX_E];
__device__ int g_eidx_i[MAX_E];
__device__ int g_bsum[512];

// ---------------------------------------------------------------------------
// CSR build
// ---------------------------------------------------------------------------
__global__ void k_zero_int(int* __restrict__ p, int n) {
    int i = blockIdx.x * blockDim.x + threadIdx.x;
    if (i < n) p[i] = 0;
}

__global__ void k_count(const int* __restrict__ dst, int* __restrict__ cnt, int E) {
    int e = blockIdx.x * blockDim.x + threadIdx.x;
    if (e < E) atomicAdd(&cnt[dst[e]], 1);
}

// block-level scan: 1024 elems/block (256 thr x 4). Writes exclusive prefixes
// and per-block totals.
__global__ void k_scan1(const int* __restrict__ cnt, int* __restrict__ rowptr,
                        int* __restrict__ bsum, int n) {
    __shared__ int s[256];
    const int t = threadIdx.x;
    const int base = blockIdx.x * 1024 + t * 4;
    int v[4], sum = 0;
#pragma unroll
    for (int j = 0; j < 4; j++) {
        v[j] = (base + j < n) ? cnt[base + j] : 0;
        sum += v[j];
    }
    s[t] = sum;
    __syncthreads();
    for (int off = 1; off < 256; off <<= 1) {
        int x = (t >= off) ? s[t - off] : 0;
        __syncthreads();
        s[t] += x;
        __syncthreads();
    }
    int run = s[t] - sum;  // exclusive prefix of this thread's chunk
    if (t == 255) bsum[blockIdx.x] = s[255];
#pragma unroll
    for (int j = 0; j < 4; j++) {
        if (base + j < n) rowptr[base + j] = run;
        run += v[j];
    }
}

__global__ void k_scan2(int* __restrict__ bsum, int nb) {
    if (threadIdx.x == 0 && blockIdx.x == 0) {
        int acc = 0;
        for (int i = 0; i < nb; i++) { int t = bsum[i]; bsum[i] = acc; acc += t; }
    }
}

__global__ void k_scan3(int* __restrict__ rowptr, const int* __restrict__ bsum,
                        int n, int E) {
    int i = blockIdx.x * blockDim.x + threadIdx.x;
    if (i < n) rowptr[i] += bsum[i >> 10];
    if (i == 0) rowptr[n] = E;
}

__global__ void k_fill(const int* __restrict__ src, const int* __restrict__ dst,
                       int* __restrict__ cursor, int* __restrict__ eidx, int E) {
    int e = blockIdx.x * blockDim.x + threadIdx.x;
    if (e >= E) return;
    int p = atomicAdd(&cursor[dst[e]], 1);
    eidx[p] = src[e];
}

// ---------------------------------------------------------------------------
// Gather aggregation: one warp per dst node; mean fused. Atomic-free.
// ---------------------------------------------------------------------------
__global__ void k_gather(const float* __restrict__ feat,
                         const int* __restrict__ rowptr,
                         const int* __restrict__ eidx,
                         float* __restrict__ agg, int N) {
    long long t = (long long)blockIdx.x * blockDim.x + threadIdx.x;
    int node = (int)(t >> 5);
    int lane = (int)(t & 31);
    if (node >= N) return;
    int s0 = rowptr[node], s1 = rowptr[node + 1];
    float4 acc = make_float4(0.f, 0.f, 0.f, 0.f);
    for (int e = s0; e < s1; e++) {
        int s = eidx[e];
        float4 v = ((const float4*)(feat + (long long)s * D))[lane];
        acc.x += v.x; acc.y += v.y; acc.z += v.z; acc.w += v.w;
    }
    float inv = 1.0f / (float)max(s1 - s0, 1);
    acc.x *= inv; acc.y *= inv; acc.z *= inv; acc.w *= inv;
    ((float4*)(agg + (long long)node * D))[lane] = acc;
}

// ---------------------------------------------------------------------------
// Fused SAGE GEMM with packed f32x2 FMA (K-pairing):
//   out[m,:] = act( agg[m,:] @ Wl^T + x[m,:] @ (Wr+Lw)^T + (bl+lb) )
// acc[i][j] is f32x2 over (k even, k odd); folded lo+hi in epilogue.
// a loads: broadcast LDS.64 from As[64][128]; w loads: LDS.64 from Ws pad-130.
// ---------------------------------------------------------------------------
__device__ __forceinline__ void ffma2(unsigned long long& d,
                                      unsigned long long a,
                                      unsigned long long b) {
    asm("fma.rn.f32x2 %0, %1, %2, %0;" : "+l"(d) : "l"(a), "l"(b));
}

#define WS_PITCH 130

__global__ __launch_bounds__(GEMM_THREADS, 2) void k_gemm(
    const float* __restrict__ agg, const float* __restrict__ x,
    const float* __restrict__ Wl, const float* __restrict__ Wr,
    const float* __restrict__ Lw,
    const float* __restrict__ bl, const float* __restrict__ lb,
    float* __restrict__ out, int M, int do_relu) {
    extern __shared__ float sm[];
    float* Ws = sm;                       // [128][WS_PITCH]
    float* As = sm + 128 * WS_PITCH;      // [64][128]

    const int tid = threadIdx.x;
    const int tx = tid & 31;   // output cols {tx, tx+32, tx+64, tx+96}
    const int ty = tid >> 5;   // output rows ty*8 .. ty*8+7
    const int row0 = blockIdx.x * TM;

    unsigned long long acc[8][4];
#pragma unroll
    for (int i = 0; i < 8; i++)
#pragma unroll
        for (int j = 0; j < 4; j++) acc[i][j] = 0ull;  // (+0.f, +0.f)

    for (int p = 0; p < 2; p++) {
        __syncthreads();
        const float* W = p ? Wr : Wl;
        for (int i = tid; i < 128 * 128; i += GEMM_THREADS) {
            float w = W[i];
            if (p) w += Lw[i];
            Ws[(i >> 7) * WS_PITCH + (i & 127)] = w;
        }
        const float* A = p ? x : agg;
        for (int i = tid; i < TM * D; i += GEMM_THREADS) {
            int r = i >> 7, k = i & 127;
            int gr = row0 + r;
            As[r * D + k] = (gr < M) ? A[(long long)gr * D + k] : 0.f;
        }
        __syncthreads();

#pragma unroll 4
        for (int kk = 0; kk < D; kk += 2) {
            unsigned long long a2[8], w2[4];
#pragma unroll
            for (int i = 0; i < 8; i++)
                a2[i] = *(const unsigned long long*)&As[(ty * 8 + i) * D + kk];
#pragma unroll
            for (int j = 0; j < 4; j++)
                w2[j] = *(const unsigned long long*)&Ws[(tx + 32 * j) * WS_PITCH + kk];
#pragma unroll
            for (int i = 0; i < 8; i++)
#pragma unroll
                for (int j = 0; j < 4; j++)
                    ffma2(acc[i][j], a2[i], w2[j]);
        }
    }

    float bias[4];
#pragma unroll
    for (int j = 0; j < 4; j++) {
        int c = tx + 32 * j;
        bias[j] = bl[c] + lb[c];
    }
#pragma unroll
    for (int i = 0; i < 8; i++) {
        int gr = row0 + ty * 8 + i;
        if (gr >= M) continue;
#pragma unroll
        for (int j = 0; j < 4; j++) {
            float lo, hi;
            asm("mov.b64 {%0,%1},%2;" : "=f"(lo), "=f"(hi) : "l"(acc[i][j]));
            float v = lo + hi + bias[j];
            if (do_relu) v = fmaxf(v, 0.f);
            out[(long long)gr * D + tx + 32 * j] = v;
        }
    }
}

// ---------------------------------------------------------------------------
// Launch
// ---------------------------------------------------------------------------
extern "C" void kernel_launch(void* const* d_in, const int* in_sizes, int n_in,
                              void* d_out, int out_size) {
    const float* x_user = (const float*)d_in[0];
    const float* x_item = (const float*)d_in[1];
    const int* ui_src = (const int*)d_in[2];
    const int* ui_dst = (const int*)d_in[3];
    const int* iu_src = (const int*)d_in[4];
    const int* iu_dst = (const int*)d_in[5];
    const float* W1l_ui = (const float*)d_in[6];
    const float* b1_ui  = (const float*)d_in[7];
    const float* W1r_ui = (const float*)d_in[8];
    const float* W1l_iu = (const float*)d_in[9];
    const float* b1_iu  = (const float*)d_in[10];
    const float* W1r_iu = (const float*)d_in[11];
    const float* L1W_u  = (const float*)d_in[12];
    const float* L1b_u  = (const float*)d_in[13];
    const float* L1W_i  = (const float*)d_in[14];
    const float* L1b_i  = (const float*)d_in[15];
    const float* W2l_ui = (const float*)d_in[16];
    const float* b2_ui  = (const float*)d_in[17];
    const float* W2r_ui = (const float*)d_in[18];
    const float* W2l_iu = (const float*)d_in[19];
    const float* b2_iu  = (const float*)d_in[20];
    const float* W2r_iu = (const float*)d_in[21];
    const float* L2W_u  = (const float*)d_in[22];
    const float* L2b_u  = (const float*)d_in[23];
    const float* L2W_i  = (const float*)d_in[24];
    const float* L2b_i  = (const float*)d_in[25];

    const int N_U = in_sizes[0] / D;
    const int N_I = in_sizes[1] / D;
    const int E   = in_sizes[2];

    float *agg_u, *agg_i, *h1_u, *h1_i;
    int *cnt_u, *cnt_i, *rp_u, *rp_i, *cur_u, *cur_i, *eidx_u, *eidx_i, *bsum;
    cudaGetSymbolAddress((void**)&agg_u, g_agg_u);
    cudaGetSymbolAddress((void**)&agg_i, g_agg_i);
    cudaGetSymbolAddress((void**)&h1_u, g_h1_u);
    cudaGetSymbolAddress((void**)&h1_i, g_h1_i);
    cudaGetSymbolAddress((void**)&cnt_u, g_cnt_u);
    cudaGetSymbolAddress((void**)&cnt_i, g_cnt_i);
    cudaGetSymbolAddress((void**)&rp_u, g_rowptr_u);
    cudaGetSymbolAddress((void**)&rp_i, g_rowptr_i);
    cudaGetSymbolAddress((void**)&cur_u, g_cursor_u);
    cudaGetSymbolAddress((void**)&cur_i, g_cursor_i);
    cudaGetSymbolAddress((void**)&eidx_u, g_eidx_u);
    cudaGetSymbolAddress((void**)&eidx_i, g_eidx_i);
    cudaGetSymbolAddress((void**)&bsum, g_bsum);

    float* out_u = (float*)d_out;
    float* out_i = out_u + (size_t)N_U * D;

    const int smem_bytes = (128 * WS_PITCH + TM * D) * (int)sizeof(float);
    cudaFuncSetAttribute(k_gemm, cudaFuncAttributeMaxDynamicSharedMemorySize,
                         smem_bytes);

    const int eb  = (E + 255) / 256;
    const int gbU = (N_U + TM - 1) / TM;
    const int gbI = (N_I + TM - 1) / TM;
    const int nbU = (N_U + 1023) / 1024;
    const int nbI = (N_I + 1023) / 1024;
    const int gaU = (N_U * 32 + 255) / 256;
    const int gaI = (N_I * 32 + 255) / 256;

    // --- CSR build (shared by both layers) ---
    k_zero_int<<<(N_U + 255) / 256, 256>>>(cnt_u, N_U);
    k_zero_int<<<(N_I + 255) / 256, 256>>>(cnt_i, N_I);
    k_count<<<eb, 256>>>(iu_dst, cnt_u, E);
    k_count<<<eb, 256>>>(ui_dst, cnt_i, E);
    k_scan1<<<nbU, 256>>>(cnt_u, rp_u, bsum, N_U);
    k_scan2<<<1, 32>>>(bsum, nbU);
    k_scan3<<<(N_U + 255) / 256, 256>>>(rp_u, bsum, N_U, E);
    k_scan1<<<nbI, 256>>>(cnt_i, rp_i, bsum, N_I);
    k_scan2<<<1, 32>>>(bsum, nbI);
    k_scan3<<<(N_I + 255) / 256, 256>>>(rp_i, bsum, N_I, E);
    cudaMemcpyAsync(cur_u, rp_u, (size_t)N_U * 4, cudaMemcpyDeviceToDevice);
    cudaMemcpyAsync(cur_i, rp_i, (size_t)N_I * 4, cudaMemcpyDeviceToDevice);
    k_fill<<<eb, 256>>>(iu_src, iu_dst, cur_u, eidx_u, E);
    k_fill<<<eb, 256>>>(ui_src, ui_dst, cur_i, eidx_i, E);

    // --- layer 1: gather + fused GEMM (relu) ---
    k_gather<<<gaU, 256>>>(x_item, rp_u, eidx_u, agg_u, N_U);
    k_gather<<<gaI, 256>>>(x_user, rp_i, eidx_i, agg_i, N_I);
    k_gemm<<<gbU, GEMM_THREADS, smem_bytes>>>(agg_u, x_user, W1l_iu, W1r_iu,
                                              L1W_u, b1_iu, L1b_u, h1_u, N_U, 1);
    k_gemm<<<gbI, GEMM_THREADS, smem_bytes>>>(agg_i, x_item, W1l_ui, W1r_ui,
                                              L1W_i, b1_ui, L1b_i, h1_i, N_I, 1);

    // --- layer 2: gather + fused GEMM (no relu) ---
    k_gather<<<gaU, 256>>>(h1_i, rp_u, eidx_u, agg_u, N_U);
    k_gather<<<gaI, 256>>>(h1_u, rp_i, eidx_i, agg_i, N_I);
    k_gemm<<<gbU, GEMM_THREADS, smem_bytes>>>(agg_u, h1_u, W2l_iu, W2r_iu,
                                              L2W_u, b2_iu, L2b_u, out_u, N_U, 0);
    k_gemm<<<gbI, GEMM_THREADS, smem_bytes>>>(agg_i, h1_i, W2l_ui, W2r_ui,
                                              L2W_i, b2_ui, L2b_i, out_i, N_I, 0);
}

// round 6
// speedup vs baseline: 2.0847x; 1.4827x over previous
#include <cuda_runtime.h>
#include <cstdint>

#define D 128
#define GT 256          // threads per tensor-GEMM CTA (8 warps)
#define PITCH 36        // u32 pitch per tile row (64 bf16 = 32 u32, +4 pad)

static const int MAX_NU = 100000;
static const int MAX_NI = 50000;
static const int MAX_E  = 300000;

// Scratch (static device globals: allocation-free at launch time)
__device__ float g_agg_u[(size_t)MAX_NU * D];
__device__ float g_agg_i[(size_t)MAX_NI * D];
__device__ float g_h1_u[(size_t)MAX_NU * D];
__device__ float g_h1_i[(size_t)MAX_NI * D];
__device__ int g_cnt_u[MAX_NU];
__device__ int g_cnt_i[MAX_NI];
__device__ int g_rowptr_u[MAX_NU + 1];
__device__ int g_rowptr_i[MAX_NI + 1];
__device__ int g_cursor_u[MAX_NU];
__device__ int g_cursor_i[MAX_NI];
__device__ int g_eidx_u[MAX_E];
__device__ int g_eidx_i[MAX_E];
__device__ int g_bsum[512];

// ---------------------------------------------------------------------------
// CSR build
// ---------------------------------------------------------------------------
__global__ void k_zero_int(int* __restrict__ p, int n) {
    int i = blockIdx.x * blockDim.x + threadIdx.x;
    if (i < n) p[i] = 0;
}
__global__ void k_count(const int* __restrict__ dst, int* __restrict__ cnt, int E) {
    int e = blockIdx.x * blockDim.x + threadIdx.x;
    if (e < E) atomicAdd(&cnt[dst[e]], 1);
}
__global__ void k_scan1(const int* __restrict__ cnt, int* __restrict__ rowptr,
                        int* __restrict__ bsum, int n) {
    __shared__ int s[256];
    const int t = threadIdx.x;
    const int base = blockIdx.x * 1024 + t * 4;
    int v[4], sum = 0;
#pragma unroll
    for (int j = 0; j < 4; j++) {
        v[j] = (base + j < n) ? cnt[base + j] : 0;
        sum += v[j];
    }
    s[t] = sum;
    __syncthreads();
    for (int off = 1; off < 256; off <<= 1) {
        int x = (t >= off) ? s[t - off] : 0;
        __syncthreads();
        s[t] += x;
        __syncthreads();
    }
    int run = s[t] - sum;
    if (t == 255) bsum[blockIdx.x] = s[255];
#pragma unroll
    for (int j = 0; j < 4; j++) {
        if (base + j < n) rowptr[base + j] = run;
        run += v[j];
    }
}
__global__ void k_scan2(int* __restrict__ bsum, int nb) {
    if (threadIdx.x == 0 && blockIdx.x == 0) {
        int acc = 0;
        for (int i = 0; i < nb; i++) { int t = bsum[i]; bsum[i] = acc; acc += t; }
    }
}
__global__ void k_scan3(int* __restrict__ rowptr, const int* __restrict__ bsum,
                        int n, int E) {
    int i = blockIdx.x * blockDim.x + threadIdx.x;
    if (i < n) rowptr[i] += bsum[i >> 10];
    if (i == 0) rowptr[n] = E;
}
__global__ void k_fill(const int* __restrict__ src, const int* __restrict__ dst,
                       int* __restrict__ cursor, int* __restrict__ eidx, int E) {
    int e = blockIdx.x * blockDim.x + threadIdx.x;
    if (e >= E) return;
    int p = atomicAdd(&cursor[dst[e]], 1);
    eidx[p] = src[e];
}

// Gather aggregation: one warp per dst node; mean fused. Atomic-free.
__global__ void k_gather(const float* __restrict__ feat,
                         const int* __restrict__ rowptr,
                         const int* __restrict__ eidx,
                         float* __restrict__ agg, int N) {
    long long t = (long long)blockIdx.x * blockDim.x + threadIdx.x;
    int node = (int)(t >> 5);
    int lane = (int)(t & 31);
    if (node >= N) return;
    int s0 = rowptr[node], s1 = rowptr[node + 1];
    float4 acc = make_float4(0.f, 0.f, 0.f, 0.f);
    for (int e = s0; e < s1; e++) {
        int s = eidx[e];
        float4 v = ((const float4*)(feat + (long long)s * D))[lane];
        acc.x += v.x; acc.y += v.y; acc.z += v.z; acc.w += v.w;
    }
    float inv = 1.0f / (float)max(s1 - s0, 1);
    acc.x *= inv; acc.y *= inv; acc.z *= inv; acc.w *= inv;
    ((float4*)(agg + (long long)node * D))[lane] = acc;
}

// ---------------------------------------------------------------------------
// bf16 split helpers
// ---------------------------------------------------------------------------
__device__ __forceinline__ uint32_t bf16_hi_bits(float f) {  // rn-bf16 bits
    uint32_t u = __float_as_uint(f);
    u = u + 0x7FFFu + ((u >> 16) & 1u);
    return u >> 16;
}
__device__ __forceinline__ float bf16_val(uint32_t b16) {
    return __uint_as_float(b16 << 16);
}
// Pack float2 into (hi2, lo2) bf16x2 split: low half = .x (even k)
__device__ __forceinline__ void split2(float2 v, uint32_t& hi2, uint32_t& lo2) {
    uint32_t hx = bf16_hi_bits(v.x), hy = bf16_hi_bits(v.y);
    hi2 = hx | (hy << 16);
    float lx = v.x - bf16_val(hx), ly = v.y - bf16_val(hy);
    lo2 = bf16_hi_bits(lx) | (bf16_hi_bits(ly) << 16);
}

__device__ __forceinline__ void mma_bf16(float* c, uint32_t a0, uint32_t a1,
                                         uint32_t a2, uint32_t a3,
                                         uint32_t b0, uint32_t b1) {
    asm volatile(
        "mma.sync.aligned.m16n8k16.row.col.f32.bf16.bf16.f32 "
        "{%0,%1,%2,%3}, {%4,%5,%6,%7}, {%8,%9}, {%0,%1,%2,%3};"
        : "+f"(c[0]), "+f"(c[1]), "+f"(c[2]), "+f"(c[3])
        : "r"(a0), "r"(a1), "r"(a2), "r"(a3), "r"(b0), "r"(b1));
}

// ---------------------------------------------------------------------------
// Tensor-core fused SAGE GEMM (bf16 split x3, K = [agg(128) | x(128)]):
//   out[m,:] = act( agg@Wl^T + x@(Wr+Lw)^T + (bl+lb) )
// CTA: 128 rows x 128 cols, 8 warps in 4x2 (warp = 32 rows x 64 cols).
// K in 4 chunks of 64. Smem tiles: A_hi/A_lo/B_hi/B_lo [128][PITCH] u32.
// ---------------------------------------------------------------------------
#define TILE_U32 (128 * PITCH)
#define SM_TOTAL (4 * TILE_U32 * 4)

__global__ __launch_bounds__(GT) void k_gemm_mma(
    const float* __restrict__ agg, const float* __restrict__ x,
    const float* __restrict__ Wl, const float* __restrict__ Wr,
    const float* __restrict__ Lw,
    const float* __restrict__ bl, const float* __restrict__ lb,
    float* __restrict__ out, int M, int do_relu) {
    extern __shared__ uint32_t sm4[];
    uint32_t* Ah = sm4;
    uint32_t* Al = sm4 + TILE_U32;
    uint32_t* Bh = sm4 + 2 * TILE_U32;
    uint32_t* Bl = sm4 + 3 * TILE_U32;

    const int tid = threadIdx.x;
    const int wid = tid >> 5;
    const int lane = tid & 31;
    const int g = lane >> 2;     // group id (0..7)
    const int q = lane & 3;      // thread in group
    const int wm = wid & 3;      // warp row (0..3): rows wm*32..+31
    const int wn = wid >> 2;     // warp col (0..1): cols wn*64..+63
    const int row0 = blockIdx.x * 128;

    float acc[2][8][4];
#pragma unroll
    for (int mt = 0; mt < 2; mt++)
#pragma unroll
        for (int nt = 0; nt < 8; nt++)
#pragma unroll
            for (int j = 0; j < 4; j++) acc[mt][nt][j] = 0.f;

    for (int c = 0; c < 4; c++) {
        __syncthreads();
        const int kof = (c & 1) * 64;
        const float* Asrc = (c < 2) ? agg : x;
        // stage A (128 rows x 64 k) as split bf16 pairs
        for (int idx = tid; idx < 128 * 32; idx += GT) {
            int r = idx >> 5, kp = idx & 31;
            int gr = row0 + r;
            float2 v = (gr < M)
                ? *(const float2*)(Asrc + (size_t)gr * D + kof + kp * 2)
                : make_float2(0.f, 0.f);
            uint32_t h2, l2;
            split2(v, h2, l2);
            Ah[r * PITCH + kp] = h2;
            Al[r * PITCH + kp] = l2;
        }
        // stage B (128 n-rows x 64 k): phase >=2 fuses Wr + Lw
        for (int idx = tid; idx < 128 * 32; idx += GT) {
            int n = idx >> 5, kp = idx & 31;
            size_t gi = (size_t)n * D + kof + kp * 2;
            float2 v;
            if (c < 2) {
                v = *(const float2*)(Wl + gi);
            } else {
                float2 a = *(const float2*)(Wr + gi);
                float2 b = *(const float2*)(Lw + gi);
                v = make_float2(a.x + b.x, a.y + b.y);
            }
            uint32_t h2, l2;
            split2(v, h2, l2);
            Bh[n * PITCH + kp] = h2;
            Bl[n * PITCH + kp] = l2;
        }
        __syncthreads();

#pragma unroll
        for (int ks = 0; ks < 4; ks++) {
            const int kb = ks * 8;  // u32 col base (16 bf16)
            uint32_t ah[2][4], al[2][4];
#pragma unroll
            for (int mt = 0; mt < 2; mt++) {
                int r0 = (wm * 32 + mt * 16 + g) * PITCH;
                int r1 = r0 + 8 * PITCH;
                ah[mt][0] = Ah[r0 + kb + q];
                ah[mt][1] = Ah[r1 + kb + q];
                ah[mt][2] = Ah[r0 + kb + q + 4];
                ah[mt][3] = Ah[r1 + kb + q + 4];
                al[mt][0] = Al[r0 + kb + q];
                al[mt][1] = Al[r1 + kb + q];
                al[mt][2] = Al[r0 + kb + q + 4];
                al[mt][3] = Al[r1 + kb + q + 4];
            }
#pragma unroll
            for (int nt = 0; nt < 8; nt++) {
                int rn = (wn * 64 + nt * 8 + g) * PITCH;
                uint32_t bh0 = Bh[rn + kb + q], bh1 = Bh[rn + kb + q + 4];
                uint32_t bl0 = Bl[rn + kb + q], bl1 = Bl[rn + kb + q + 4];
#pragma unroll
                for (int mt = 0; mt < 2; mt++) {
                    mma_bf16(acc[mt][nt], ah[mt][0], ah[mt][1], ah[mt][2],
                             ah[mt][3], bh0, bh1);
                    mma_bf16(acc[mt][nt], ah[mt][0], ah[mt][1], ah[mt][2],
                             ah[mt][3], bl0, bl1);
                    mma_bf16(acc[mt][nt], al[mt][0], al[mt][1], al[mt][2],
                             al[mt][3], bh0, bh1);
                }
            }
        }
    }

    // Epilogue: fused double-bias + optional ReLU, float2 stores
#pragma unroll
    for (int nt = 0; nt < 8; nt++) {
        int col = wn * 64 + nt * 8 + q * 2;
        float b0 = bl[col] + lb[col];
        float b1 = bl[col + 1] + lb[col + 1];
#pragma unroll
        for (int mt = 0; mt < 2; mt++) {
            int r0 = row0 + wm * 32 + mt * 16 + g;
            float* a = acc[mt][nt];
            if (r0 < M) {
                float2 v = make_float2(a[0] + b0, a[1] + b1);
                if (do_relu) { v.x = fmaxf(v.x, 0.f); v.y = fmaxf(v.y, 0.f); }
                *(float2*)(out + (size_t)r0 * D + col) = v;
            }
            int r1 = r0 + 8;
            if (r1 < M) {
                float2 v = make_float2(a[2] + b0, a[3] + b1);
                if (do_relu) { v.x = fmaxf(v.x, 0.f); v.y = fmaxf(v.y, 0.f); }
                *(float2*)(out + (size_t)r1 * D + col) = v;
            }
        }
    }
}

// ---------------------------------------------------------------------------
// Launch
// ---------------------------------------------------------------------------
extern "C" void kernel_launch(void* const* d_in, const int* in_sizes, int n_in,
                              void* d_out, int out_size) {
    const float* x_user = (const float*)d_in[0];
    const float* x_item = (const float*)d_in[1];
    const int* ui_src = (const int*)d_in[2];
    const int* ui_dst = (const int*)d_in[3];
    const int* iu_src = (const int*)d_in[4];
    const int* iu_dst = (const int*)d_in[5];
    const float* W1l_ui = (const float*)d_in[6];
    const float* b1_ui  = (const float*)d_in[7];
    const float* W1r_ui = (const float*)d_in[8];
    const float* W1l_iu = (const float*)d_in[9];
    const float* b1_iu  = (const float*)d_in[10];
    const float* W1r_iu = (const float*)d_in[11];
    const float* L1W_u  = (const float*)d_in[12];
    const float* L1b_u  = (const float*)d_in[13];
    const float* L1W_i  = (const float*)d_in[14];
    const float* L1b_i  = (const float*)d_in[15];
    const float* W2l_ui = (const float*)d_in[16];
    const float* b2_ui  = (const float*)d_in[17];
    const float* W2r_ui = (const float*)d_in[18];
    const float* W2l_iu = (const float*)d_in[19];
    const float* b2_iu  = (const float*)d_in[20];
    const float* W2r_iu = (const float*)d_in[21];
    const float* L2W_u  = (const float*)d_in[22];
    const float* L2b_u  = (const float*)d_in[23];
    const float* L2W_i  = (const float*)d_in[24];
    const float* L2b_i  = (const float*)d_in[25];

    const int N_U = in_sizes[0] / D;
    const int N_I = in_sizes[1] / D;
    const int E   = in_sizes[2];

    float *agg_u, *agg_i, *h1_u, *h1_i;
    int *cnt_u, *cnt_i, *rp_u, *rp_i, *cur_u, *cur_i, *eidx_u, *eidx_i, *bsum;
    cudaGetSymbolAddress((void**)&agg_u, g_agg_u);
    cudaGetSymbolAddress((void**)&agg_i, g_agg_i);
    cudaGetSymbolAddress((void**)&h1_u, g_h1_u);
    cudaGetSymbolAddress((void**)&h1_i, g_h1_i);
    cudaGetSymbolAddress((void**)&cnt_u, g_cnt_u);
    cudaGetSymbolAddress((void**)&cnt_i, g_cnt_i);
    cudaGetSymbolAddress((void**)&rp_u, g_rowptr_u);
    cudaGetSymbolAddress((void**)&rp_i, g_rowptr_i);
    cudaGetSymbolAddress((void**)&cur_u, g_cursor_u);
    cudaGetSymbolAddress((void**)&cur_i, g_cursor_i);
    cudaGetSymbolAddress((void**)&eidx_u, g_eidx_u);
    cudaGetSymbolAddress((void**)&eidx_i, g_eidx_i);
    cudaGetSymbolAddress((void**)&bsum, g_bsum);

    float* out_u = (float*)d_out;
    float* out_i = out_u + (size_t)N_U * D;

    cudaFuncSetAttribute(k_gemm_mma, cudaFuncAttributeMaxDynamicSharedMemorySize,
                         SM_TOTAL);

    const int eb  = (E + 255) / 256;
    const int nbU = (N_U + 1023) / 1024;
    const int nbI = (N_I + 1023) / 1024;
    const int gaU = (N_U * 32 + 255) / 256;
    const int gaI = (N_I * 32 + 255) / 256;
    const int gbU = (N_U + 127) / 128;
    const int gbI = (N_I + 127) / 128;

    // --- CSR build (shared by both layers) ---
    k_zero_int<<<(N_U + 255) / 256, 256>>>(cnt_u, N_U);
    k_zero_int<<<(N_I + 255) / 256, 256>>>(cnt_i, N_I);
    k_count<<<eb, 256>>>(iu_dst, cnt_u, E);
    k_count<<<eb, 256>>>(ui_dst, cnt_i, E);
    k_scan1<<<nbU, 256>>>(cnt_u, rp_u, bsum, N_U);
    k_scan2<<<1, 32>>>(bsum, nbU);
    k_scan3<<<(N_U + 255) / 256, 256>>>(rp_u, bsum, N_U, E);
    k_scan1<<<nbI, 256>>>(cnt_i, rp_i, bsum, N_I);
    k_scan2<<<1, 32>>>(bsum, nbI);
    k_scan3<<<(N_I + 255) / 256, 256>>>(rp_i, bsum, N_I, E);
    cudaMemcpyAsync(cur_u, rp_u, (size_t)N_U * 4, cudaMemcpyDeviceToDevice);
    cudaMemcpyAsync(cur_i, rp_i, (size_t)N_I * 4, cudaMemcpyDeviceToDevice);
    k_fill<<<eb, 256>>>(iu_src, iu_dst, cur_u, eidx_u, E);
    k_fill<<<eb, 256>>>(ui_src, ui_dst, cur_i, eidx_i, E);

    // --- layer 1: gather + fused tensor GEMM (relu) ---
    k_gather<<<gaU, 256>>>(x_item, rp_u, eidx_u, agg_u, N_U);
    k_gather<<<gaI, 256>>>(x_user, rp_i, eidx_i, agg_i, N_I);
    k_gemm_mma<<<gbU, GT, SM_TOTAL>>>(agg_u, x_user, W1l_iu, W1r_iu, L1W_u,
                                      b1_iu, L1b_u, h1_u, N_U, 1);
    k_gemm_mma<<<gbI, GT, SM_TOTAL>>>(agg_i, x_item, W1l_ui, W1r_ui, L1W_i,
                                      b1_ui, L1b_i, h1_i, N_I, 1);

    // --- layer 2: gather + fused tensor GEMM (no relu) ---
    k_gather<<<gaU, 256>>>(h1_i, rp_u, eidx_u, agg_u, N_U);
    k_gather<<<gaI, 256>>>(h1_u, rp_i, eidx_i, agg_i, N_I);
    k_gemm_mma<<<gbU, GT, SM_TOTAL>>>(agg_u, h1_u, W2l_iu, W2r_iu, L2W_u,
                                      b2_iu, L2b_u, out_u, N_U, 0);
    k_gemm_mma<<<gbI, GT, SM_TOTAL>>>(agg_i, h1_i, W2l_ui, W2r_ui, L2W_i,
                                      b2_ui, L2b_i, out_i, N_I, 0);
}

// round 7
// speedup vs baseline: 2.9475x; 1.4139x over previous
#include <cuda_runtime.h>
#include <cstdint>

#define D 128
#define DP 64           // u32 pairs per feature row
#define GT 256          // threads per tensor-GEMM CTA (8 warps)
#define PITCH 36        // u32 pitch per smem tile row (32 data + 4 pad)

static const int MAX_NU = 100000;
static const int MAX_NI = 50000;
static const int MAX_E  = 300000;

// Split-bf16 buffers (hi/lo u32 per float pair). Same byte volume as fp32.
__device__ uint32_t g_xu_h[(size_t)MAX_NU * DP], g_xu_l[(size_t)MAX_NU * DP];
__device__ uint32_t g_xi_h[(size_t)MAX_NI * DP], g_xi_l[(size_t)MAX_NI * DP];
__device__ uint32_t g_au_h[(size_t)MAX_NU * DP], g_au_l[(size_t)MAX_NU * DP];
__device__ uint32_t g_ai_h[(size_t)MAX_NI * DP], g_ai_l[(size_t)MAX_NI * DP];
__device__ uint32_t g_hu_h[(size_t)MAX_NU * DP], g_hu_l[(size_t)MAX_NU * DP];
__device__ uint32_t g_hi_h[(size_t)MAX_NI * DP], g_hi_l[(size_t)MAX_NI * DP];
__device__ uint32_t g_w_h[4 * 128 * 128], g_w_l[4 * 128 * 128];
// CSR scratch
__device__ int g_cnt_u[MAX_NU];
__device__ int g_cnt_i[MAX_NI];
__device__ int g_rowptr_u[MAX_NU + 1];
__device__ int g_rowptr_i[MAX_NI + 1];
__device__ int g_cursor_u[MAX_NU];
__device__ int g_cursor_i[MAX_NI];
__device__ int g_eidx_u[MAX_E];
__device__ int g_eidx_i[MAX_E];
__device__ int g_bsum[512];

// ---------------------------------------------------------------------------
// Helpers
// ---------------------------------------------------------------------------
// Fast split: v -> (hi bf16x2, lo bf16x2); low half = v.x
__device__ __forceinline__ void split2f(float2 v, uint32_t& h2, uint32_t& l2) {
    asm("cvt.rn.bf16x2.f32 %0, %1, %2;" : "=r"(h2) : "f"(v.y), "f"(v.x));
    float hx = __uint_as_float(h2 << 16);
    float hy = __uint_as_float(h2 & 0xFFFF0000u);
    float lx = v.x - hx, ly = v.y - hy;
    asm("cvt.rn.bf16x2.f32 %0, %1, %2;" : "=r"(l2) : "f"(ly), "f"(lx));
}
// Reconstruct 2 floats from split pair
__device__ __forceinline__ float2 join2f(uint32_t h2, uint32_t l2) {
    float2 v;
    v.x = __uint_as_float(h2 << 16) + __uint_as_float(l2 << 16);
    v.y = __uint_as_float(h2 & 0xFFFF0000u) + __uint_as_float(l2 & 0xFFFF0000u);
    return v;
}
__device__ __forceinline__ void cp16(void* dst, const void* src) {
    uint32_t d = (uint32_t)__cvta_generic_to_shared(dst);
    asm volatile("cp.async.cg.shared.global [%0], [%1], 16;" :: "r"(d), "l"(src));
}
__device__ __forceinline__ void mma_bf16(float* c, uint32_t a0, uint32_t a1,
                                         uint32_t a2, uint32_t a3,
                                         uint32_t b0, uint32_t b1) {
    asm volatile(
        "mma.sync.aligned.m16n8k16.row.col.f32.bf16.bf16.f32 "
        "{%0,%1,%2,%3}, {%4,%5,%6,%7}, {%8,%9}, {%0,%1,%2,%3};"
        : "+f"(c[0]), "+f"(c[1]), "+f"(c[2]), "+f"(c[3])
        : "r"(a0), "r"(a1), "r"(a2), "r"(a3), "r"(b0), "r"(b1));
}

// ---------------------------------------------------------------------------
// CSR build
// ---------------------------------------------------------------------------
__global__ void k_zero_int(int* __restrict__ p, int n) {
    int i = blockIdx.x * blockDim.x + threadIdx.x;
    if (i < n) p[i] = 0;
}
__global__ void k_count(const int* __restrict__ dst, int* __restrict__ cnt, int E) {
    int e = blockIdx.x * blockDim.x + threadIdx.x;
    if (e < E) atomicAdd(&cnt[dst[e]], 1);
}
__global__ void k_scan1(const int* __restrict__ cnt, int* __restrict__ rowptr,
                        int* __restrict__ bsum, int n) {
    __shared__ int s[256];
    const int t = threadIdx.x;
    const int base = blockIdx.x * 1024 + t * 4;
    int v[4], sum = 0;
#pragma unroll
    for (int j = 0; j < 4; j++) {
        v[j] = (base + j < n) ? cnt[base + j] : 0;
        sum += v[j];
    }
    s[t] = sum;
    __syncthreads();
    for (int off = 1; off < 256; off <<= 1) {
        int x = (t >= off) ? s[t - off] : 0;
        __syncthreads();
        s[t] += x;
        __syncthreads();
    }
    int run = s[t] - sum;
    if (t == 255) bsum[blockIdx.x] = s[255];
#pragma unroll
    for (int j = 0; j < 4; j++) {
        if (base + j < n) rowptr[base + j] = run;
        run += v[j];
    }
}
__global__ void k_scan2(int* __restrict__ bsum, int nb) {
    if (threadIdx.x == 0 && blockIdx.x == 0) {
        int acc = 0;
        for (int i = 0; i < nb; i++) { int t = bsum[i]; bsum[i] = acc; acc += t; }
    }
}
__global__ void k_scan3(int* __restrict__ rowptr, const int* __restrict__ bsum,
                        int n, int E) {
    int i = blockIdx.x * blockDim.x + threadIdx.x;
    if (i < n) rowptr[i] += bsum[i >> 10];
    if (i == 0) rowptr[n] = E;
}
__global__ void k_fill(const int* __restrict__ src, const int* __restrict__ dst,
                       int* __restrict__ cursor, int* __restrict__ eidx, int E) {
    int e = blockIdx.x * blockDim.x + threadIdx.x;
    if (e >= E) return;
    int p = atomicAdd(&cursor[dst[e]], 1);
    eidx[p] = src[e];
}

// ---------------------------------------------------------------------------
// One-time conversions
// ---------------------------------------------------------------------------
__global__ void k_convert(const float* __restrict__ x, uint32_t* __restrict__ h,
                          uint32_t* __restrict__ l, int npairs) {
    int i = blockIdx.x * blockDim.x + threadIdx.x;
    if (i >= npairs) return;
    float2 v = ((const float2*)x)[i];
    uint32_t h2, l2;
    split2f(v, h2, l2);
    h[i] = h2;
    l[i] = l2;
}
// Weight prep: Wcat[n][k] = k<128 ? Wl[n][k] : Wr[n][k-128]+Lw[n][k-128], split.
__global__ void k_wprep(const float* __restrict__ Wl, const float* __restrict__ Wr,
                        const float* __restrict__ Lw, uint32_t* __restrict__ oh,
                        uint32_t* __restrict__ ol) {
    int idx = blockIdx.x * blockDim.x + threadIdx.x;
    if (idx >= 128 * 128) return;
    int n = idx >> 7, kp = idx & 127;
    float2 v;
    if (kp < 64) {
        v = *(const float2*)(Wl + n * 128 + kp * 2);
    } else {
        const float2 a = *(const float2*)(Wr + n * 128 + (kp - 64) * 2);
        const float2 b = *(const float2*)(Lw + n * 128 + (kp - 64) * 2);
        v = make_float2(a.x + b.x, a.y + b.y);
    }
    uint32_t h2, l2;
    split2f(v, h2, l2);
    oh[idx] = h2;
    ol[idx] = l2;
}

// ---------------------------------------------------------------------------
// Gather (split in, split out): one warp per dst node; mean fused.
// ---------------------------------------------------------------------------
__global__ void k_gather(const uint32_t* __restrict__ fh,
                         const uint32_t* __restrict__ fl,
                         const int* __restrict__ rowptr,
                         const int* __restrict__ eidx,
                         uint32_t* __restrict__ oh, uint32_t* __restrict__ ol,
                         int N) {
    long long t = (long long)blockIdx.x * blockDim.x + threadIdx.x;
    int node = (int)(t >> 5);
    int lane = (int)(t & 31);
    if (node >= N) return;
    int s0 = rowptr[node], s1 = rowptr[node + 1];
    float a0 = 0.f, a1 = 0.f, a2 = 0.f, a3 = 0.f;
    for (int e = s0; e < s1; e++) {
        size_t base = (size_t)eidx[e] * DP + lane * 2;
        uint2 h = *(const uint2*)(fh + base);
        uint2 l = *(const uint2*)(fl + base);
        float2 p0 = join2f(h.x, l.x);
        float2 p1 = join2f(h.y, l.y);
        a0 += p0.x; a1 += p0.y; a2 += p1.x; a3 += p1.y;
    }
    float inv = 1.0f / (float)max(s1 - s0, 1);
    uint2 ho, lo;
    split2f(make_float2(a0 * inv, a1 * inv), ho.x, lo.x);
    split2f(make_float2(a2 * inv, a3 * inv), ho.y, lo.y);
    size_t ob = (size_t)node * DP + lane * 2;
    *(uint2*)(oh + ob) = ho;
    *(uint2*)(ol + ob) = lo;
}

// ---------------------------------------------------------------------------
// Tensor-core fused SAGE GEMM (bf16 split x3, all operands pre-split):
//   out[m,:] = act( agg@Wl^T + x@(Wr+Lw)^T + (bl+lb) )
// Staging = pure cp.async 16B copies. CTA: 128x128, 8 warps (4x2).
// mode 1: relu + split store (h1). mode 0: fp32 store (final out).
// ---------------------------------------------------------------------------
#define TILE_U32 (128 * PITCH)
#define SM_TOTAL (4 * TILE_U32 * 4)

__global__ __launch_bounds__(GT) void k_gemm_mma(
    const uint32_t* __restrict__ aggh, const uint32_t* __restrict__ aggl,
    const uint32_t* __restrict__ xh, const uint32_t* __restrict__ xl,
    const uint32_t* __restrict__ Wh, const uint32_t* __restrict__ Wlo,
    const float* __restrict__ bl, const float* __restrict__ lb,
    float* __restrict__ outf, uint32_t* __restrict__ oh,
    uint32_t* __restrict__ ol, int M, int mode) {
    extern __shared__ uint32_t sm4[];
    uint32_t* Ah = sm4;
    uint32_t* Al = sm4 + TILE_U32;
    uint32_t* Bh = sm4 + 2 * TILE_U32;
    uint32_t* Bl = sm4 + 3 * TILE_U32;

    const int tid = threadIdx.x;
    const int wid = tid >> 5;
    const int lane = tid & 31;
    const int g = lane >> 2;
    const int q = lane & 3;
    const int wm = wid & 3;
    const int wn = wid >> 2;
    const int row0 = blockIdx.x * 128;

    float acc[2][8][4];
#pragma unroll
    for (int mt = 0; mt < 2; mt++)
#pragma unroll
        for (int nt = 0; nt < 8; nt++)
#pragma unroll
            for (int j = 0; j < 4; j++) acc[mt][nt][j] = 0.f;

    for (int c = 0; c < 4; c++) {
        __syncthreads();  // previous MMA done reading tiles
        const uint32_t* Ash = (c < 2) ? aggh : xh;
        const uint32_t* Asl = (c < 2) ? aggl : xl;
        const int kofA = (c & 1) * 32;      // u32 col offset in DP-wide row
        const int kofW = c * 32;            // u32 col offset in 128-wide W row
        for (int i = tid; i < 1024; i += GT) {
            int r = i >> 3, c4 = (i & 7) * 4;
            int toff = r * PITCH + c4;
            cp16(Bh + toff, Wh + r * 128 + kofW + c4);
            cp16(Bl + toff, Wlo + r * 128 + kofW + c4);
            int gr = row0 + r;
            if (gr < M) {
                size_t s = (size_t)gr * DP + kofA + c4;
                cp16(Ah + toff, Ash + s);
                cp16(Al + toff, Asl + s);
            } else {
                *(uint4*)(Ah + toff) = make_uint4(0, 0, 0, 0);
                *(uint4*)(Al + toff) = make_uint4(0, 0, 0, 0);
            }
        }
        asm volatile("cp.async.commit_group;");
        asm volatile("cp.async.wait_group 0;");
        __syncthreads();

#pragma unroll
        for (int ks = 0; ks < 4; ks++) {
            const int kb = ks * 8;
            uint32_t ah[2][4], al[2][4];
#pragma unroll
            for (int mt = 0; mt < 2; mt++) {
                int r0 = (wm * 32 + mt * 16 + g) * PITCH;
                int r1 = r0 + 8 * PITCH;
                ah[mt][0] = Ah[r0 + kb + q];
                ah[mt][1] = Ah[r1 + kb + q];
                ah[mt][2] = Ah[r0 + kb + q + 4];
                ah[mt][3] = Ah[r1 + kb + q + 4];
                al[mt][0] = Al[r0 + kb + q];
                al[mt][1] = Al[r1 + kb + q];
                al[mt][2] = Al[r0 + kb + q + 4];
                al[mt][3] = Al[r1 + kb + q + 4];
            }
#pragma unroll
            for (int nt = 0; nt < 8; nt++) {
                int rn = (wn * 64 + nt * 8 + g) * PITCH;
                uint32_t bh0 = Bh[rn + kb + q], bh1 = Bh[rn + kb + q + 4];
                uint32_t bl0 = Bl[rn + kb + q], bl1 = Bl[rn + kb + q + 4];
#pragma unroll
                for (int mt = 0; mt < 2; mt++) {
                    mma_bf16(acc[mt][nt], ah[mt][0], ah[mt][1], ah[mt][2],
                             ah[mt][3], bh0, bh1);
                    mma_bf16(acc[mt][nt], ah[mt][0], ah[mt][1], ah[mt][2],
                             ah[mt][3], bl0, bl1);
                    mma_bf16(acc[mt][nt], al[mt][0], al[mt][1], al[mt][2],
                             al[mt][3], bh0, bh1);
                }
            }
        }
    }

    // Epilogue: fused double-bias (+ReLU+split for mode 1)
#pragma unroll
    for (int nt = 0; nt < 8; nt++) {
        int col = wn * 64 + nt * 8 + q * 2;
        float b0 = bl[col] + lb[col];
        float b1 = bl[col + 1] + lb[col + 1];
#pragma unroll
        for (int mt = 0; mt < 2; mt++) {
            float* a = acc[mt][nt];
#pragma unroll
            for (int hh = 0; hh < 2; hh++) {
                int gr = row0 + wm * 32 + mt * 16 + g + hh * 8;
                if (gr >= M) continue;
                float v0 = a[hh * 2 + 0] + b0;
                float v1 = a[hh * 2 + 1] + b1;
                if (mode == 1) {
                    v0 = fmaxf(v0, 0.f);
                    v1 = fmaxf(v1, 0.f);
                    uint32_t h2, l2;
                    split2f(make_float2(v0, v1), h2, l2);
                    size_t ob = (size_t)gr * DP + (col >> 1);
                    oh[ob] = h2;
                    ol[ob] = l2;
                } else {
                    *(float2*)(outf + (size_t)gr * D + col) = make_float2(v0, v1);
                }
            }
        }
    }
}

// ---------------------------------------------------------------------------
// Launch
// ---------------------------------------------------------------------------
extern "C" void kernel_launch(void* const* d_in, const int* in_sizes, int n_in,
                              void* d_out, int out_size) {
    const float* x_user = (const float*)d_in[0];
    const float* x_item = (const float*)d_in[1];
    const int* ui_src = (const int*)d_in[2];
    const int* ui_dst = (const int*)d_in[3];
    const int* iu_src = (const int*)d_in[4];
    const int* iu_dst = (const int*)d_in[5];
    const float* W1l_ui = (const float*)d_in[6];
    const float* b1_ui  = (const float*)d_in[7];
    const float* W1r_ui = (const float*)d_in[8];
    const float* W1l_iu = (const float*)d_in[9];
    const float* b1_iu  = (const float*)d_in[10];
    const float* W1r_iu = (const float*)d_in[11];
    const float* L1W_u  = (const float*)d_in[12];
    const float* L1b_u  = (const float*)d_in[13];
    const float* L1W_i  = (const float*)d_in[14];
    const float* L1b_i  = (const float*)d_in[15];
    const float* W2l_ui = (const float*)d_in[16];
    const float* b2_ui  = (const float*)d_in[17];
    const float* W2r_ui = (const float*)d_in[18];
    const float* W2l_iu = (const float*)d_in[19];
    const float* b2_iu  = (const float*)d_in[20];
    const float* W2r_iu = (const float*)d_in[21];
    const float* L2W_u  = (const float*)d_in[22];
    const float* L2b_u  = (const float*)d_in[23];
    const float* L2W_i  = (const float*)d_in[24];
    const float* L2b_i  = (const float*)d_in[25];

    const int N_U = in_sizes[0] / D;
    const int N_I = in_sizes[1] / D;
    const int E   = in_sizes[2];

    uint32_t *xu_h, *xu_l, *xi_h, *xi_l, *au_h, *au_l, *ai_h, *ai_l;
    uint32_t *hu_h, *hu_l, *hi_h, *hi_l, *w_h, *w_l;
    int *cnt_u, *cnt_i, *rp_u, *rp_i, *cur_u, *cur_i, *eidx_u, *eidx_i, *bsum;
    cudaGetSymbolAddress((void**)&xu_h, g_xu_h);
    cudaGetSymbolAddress((void**)&xu_l, g_xu_l);
    cudaGetSymbolAddress((void**)&xi_h, g_xi_h);
    cudaGetSymbolAddress((void**)&xi_l, g_xi_l);
    cudaGetSymbolAddress((void**)&au_h, g_au_h);
    cudaGetSymbolAddress((void**)&au_l, g_au_l);
    cudaGetSymbolAddress((void**)&ai_h, g_ai_h);
    cudaGetSymbolAddress((void**)&ai_l, g_ai_l);
    cudaGetSymbolAddress((void**)&hu_h, g_hu_h);
    cudaGetSymbolAddress((void**)&hu_l, g_hu_l);
    cudaGetSymbolAddress((void**)&hi_h, g_hi_h);
    cudaGetSymbolAddress((void**)&hi_l, g_hi_l);
    cudaGetSymbolAddress((void**)&w_h, g_w_h);
    cudaGetSymbolAddress((void**)&w_l, g_w_l);
    cudaGetSymbolAddress((void**)&cnt_u, g_cnt_u);
    cudaGetSymbolAddress((void**)&cnt_i, g_cnt_i);
    cudaGetSymbolAddress((void**)&rp_u, g_rowptr_u);
    cudaGetSymbolAddress((void**)&rp_i, g_rowptr_i);
    cudaGetSymbolAddress((void**)&cur_u, g_cursor_u);
    cudaGetSymbolAddress((void**)&cur_i, g_cursor_i);
    cudaGetSymbolAddress((void**)&eidx_u, g_eidx_u);
    cudaGetSymbolAddress((void**)&eidx_i, g_eidx_i);
    cudaGetSymbolAddress((void**)&bsum, g_bsum);

    float* out_u = (float*)d_out;
    float* out_i = out_u + (size_t)N_U * D;

    cudaFuncSetAttribute(k_gemm_mma, cudaFuncAttributeMaxDynamicSharedMemorySize,
                         SM_TOTAL);

    const int eb  = (E + 255) / 256;
    const int nbU = (N_U + 1023) / 1024;
    const int nbI = (N_I + 1023) / 1024;
    const int gaU = (N_U * 32 + 255) / 256;
    const int gaI = (N_I * 32 + 255) / 256;
    const int gbU = (N_U + 127) / 128;
    const int gbI = (N_I + 127) / 128;
    const int cvU = (N_U * DP + 255) / 256;
    const int cvI = (N_I * DP + 255) / 256;
    const int wb  = (128 * 128 + 255) / 256;

    // --- one-time conversions (independent of CSR) ---
    k_convert<<<cvU, 256>>>(x_user, xu_h, xu_l, N_U * DP);
    k_convert<<<cvI, 256>>>(x_item, xi_h, xi_l, N_I * DP);
    k_wprep<<<wb, 256>>>(W1l_iu, W1r_iu, L1W_u, w_h + 0 * 16384, w_l + 0 * 16384);
    k_wprep<<<wb, 256>>>(W1l_ui, W1r_ui, L1W_i, w_h + 1 * 16384, w_l + 1 * 16384);
    k_wprep<<<wb, 256>>>(W2l_iu, W2r_iu, L2W_u, w_h + 2 * 16384, w_l + 2 * 16384);
    k_wprep<<<wb, 256>>>(W2l_ui, W2r_ui, L2W_i, w_h + 3 * 16384, w_l + 3 * 16384);

    // --- CSR build (shared by both layers) ---
    k_zero_int<<<(N_U + 255) / 256, 256>>>(cnt_u, N_U);
    k_zero_int<<<(N_I + 255) / 256, 256>>>(cnt_i, N_I);
    k_count<<<eb, 256>>>(iu_dst, cnt_u, E);
    k_count<<<eb, 256>>>(ui_dst, cnt_i, E);
    k_scan1<<<nbU, 256>>>(cnt_u, rp_u, bsum, N_U);
    k_scan2<<<1, 32>>>(bsum, nbU);
    k_scan3<<<(N_U + 255) / 256, 256>>>(rp_u, bsum, N_U, E);
    k_scan1<<<nbI, 256>>>(cnt_i, rp_i, bsum, N_I);
    k_scan2<<<1, 32>>>(bsum, nbI);
    k_scan3<<<(N_I + 255) / 256, 256>>>(rp_i, bsum, N_I, E);
    cudaMemcpyAsync(cur_u, rp_u, (size_t)N_U * 4, cudaMemcpyDeviceToDevice);
    cudaMemcpyAsync(cur_i, rp_i, (size_t)N_I * 4, cudaMemcpyDeviceToDevice);
    k_fill<<<eb, 256>>>(iu_src, iu_dst, cur_u, eidx_u, E);
    k_fill<<<eb, 256>>>(ui_src, ui_dst, cur_i, eidx_i, E);

    // --- layer 1: gather + GEMM (relu, split h1 out) ---
    k_gather<<<gaU, 256>>>(xi_h, xi_l, rp_u, eidx_u, au_h, au_l, N_U);
    k_gather<<<gaI, 256>>>(xu_h, xu_l, rp_i, eidx_i, ai_h, ai_l, N_I);
    k_gemm_mma<<<gbU, GT, SM_TOTAL>>>(au_h, au_l, xu_h, xu_l,
                                      w_h + 0 * 16384, w_l + 0 * 16384,
                                      b1_iu, L1b_u, nullptr, hu_h, hu_l, N_U, 1);
    k_gemm_mma<<<gbI, GT, SM_TOTAL>>>(ai_h, ai_l, xi_h, xi_l,
                                      w_h + 1 * 16384, w_l + 1 * 16384,
                                      b1_ui, L1b_i, nullptr, hi_h, hi_l, N_I, 1);

    // --- layer 2: gather + GEMM (fp32 out, no relu) ---
    k_gather<<<gaU, 256>>>(hi_h, hi_l, rp_u, eidx_u, au_h, au_l, N_U);
    k_gather<<<gaI, 256>>>(hu_h, hu_l, rp_i, eidx_i, ai_h, ai_l, N_I);
    k_gemm_mma<<<gbU, GT, SM_TOTAL>>>(au_h, au_l, hu_h, hu_l,
                                      w_h + 2 * 16384, w_l + 2 * 16384,
                                      b2_iu, L2b_u, out_u, nullptr, nullptr, N_U, 0);
    k_gemm_mma<<<gbI, GT, SM_TOTAL>>>(ai_h, ai_l, hi_h, hi_l,
                                      w_h + 3 * 16384, w_l + 3 * 16384,
                                      b2_ui, L2b_i, out_i, nullptr, nullptr, N_I, 0);
}